// round 8
// baseline (speedup 1.0000x reference)
#include <cuda_runtime.h>

// Problem constants (fixed by the dataset): B=256, T=512, K=128
#define Bn 256
#define Tn 512
#define Kn 128

// Device scratch (no allocs allowed).
__device__ float g_partial[Bn];
__device__ int   g_perm[Bn];   // g_perm[rank] = batch index, by seq_len
__device__ int   g_done;       // zero-init; last CTA resets to 0 each run

// ---- packed f32x2 helpers (sm_103a) ---------------------------------------
__device__ __forceinline__ unsigned long long fma2(unsigned long long a,
                                                   unsigned long long b,
                                                   unsigned long long c) {
    unsigned long long d;
    asm("fma.rn.f32x2 %0, %1, %2, %3;" : "=l"(d) : "l"(a), "l"(b), "l"(c));
    return d;
}
__device__ __forceinline__ unsigned long long add2(unsigned long long a,
                                                   unsigned long long b) {
    unsigned long long d;
    asm("add.rn.f32x2 %0, %1, %2;" : "=l"(d) : "l"(a), "l"(b));
    return d;
}
__device__ __forceinline__ unsigned long long pack2(float lo, float hi) {
    unsigned long long d;
    asm("mov.b64 %0, {%1, %2};" : "=l"(d) : "f"(lo), "f"(hi));
    return d;
}
__device__ __forceinline__ float2 unpack2(unsigned long long v) {
    float lo, hi;
    asm("mov.b64 {%0, %1}, %2;" : "=f"(lo), "=f"(hi) : "l"(v));
    return make_float2(lo, hi);
}

// ---- scheduler: grid=32 x 256 threads; warp w ranks batch 8*bx+w ----------
__global__ void crf_sched_kernel(const int* __restrict__ seq_lens)
{
    const int lane = threadIdx.x & 31;
    const int i    = blockIdx.x * 8 + (threadIdx.x >> 5);
    const int Li   = seq_lens[i];
    int r = 0;
    #pragma unroll
    for (int kk = 0; kk < 8; kk++) {
        int k  = lane + 32 * kk;
        int Lk = seq_lens[k];
        r += (Lk < Li) || (Lk == Li && k < i);   // unique ranks
    }
    #pragma unroll
    for (int o = 16; o; o >>= 1) r += __shfl_xor_sync(0xffffffffu, r, o);
    if (lane == 0) g_perm[r] = i;
}

// Fused step: advance BOTH batches one step. Two independent accumulator
// chains share eT2 -> ILP hides FMA/LDS latency. RENORM rescales each batch
// by its stale beta[0] (exact LSE shift; growth bounded << e^88 over 4 steps).
#define CRF_STEP2(LOA, LOB, RENORM) do {                                     \
    const float* bpA_ = sh_beta[0][curA];                                    \
    const float* bpB_ = sh_beta[1][curB];                                    \
    float cjA_, cjB_;                                                        \
    if (RENORM) {                                                            \
        float lrA_ = __logf(bpA_[0]);                                        \
        float lrB_ = __logf(bpB_[0]);                                        \
        SA += lrA_; SB += lrB_;                                              \
        cjA_ = __expf((LOA) - lrA_);                                         \
        cjB_ = __expf((LOB) - lrB_);                                         \
    } else {                                                                 \
        cjA_ = __expf(LOA);                                                  \
        cjB_ = __expf(LOB);                                                  \
    }                                                                        \
    const double2* apA_ = (const double2*)(bpA_ + 68 * h);                   \
    const double2* apB_ = (const double2*)(bpB_ + 68 * h);                   \
    unsigned long long a0_=0,a1_=0,a2_=0,a3_=0,b0_=0,b1_=0,b2_=0,b3_=0;      \
    _Pragma("unroll")                                                        \
    for (int k_ = 0; k_ < 8; k_++) {                                         \
        double2 xA_ = apA_[2*k_], yA_ = apA_[2*k_+1];   /* LDS.128 bcast */  \
        double2 xB_ = apB_[2*k_], yB_ = apB_[2*k_+1];                        \
        a0_ = fma2(__double_as_longlong(xA_.x), eT2[4*k_+0], a0_);           \
        b0_ = fma2(__double_as_longlong(xB_.x), eT2[4*k_+0], b0_);           \
        a1_ = fma2(__double_as_longlong(xA_.y), eT2[4*k_+1], a1_);           \
        b1_ = fma2(__double_as_longlong(xB_.y), eT2[4*k_+1], b1_);           \
        a2_ = fma2(__double_as_longlong(yA_.x), eT2[4*k_+2], a2_);           \
        b2_ = fma2(__double_as_longlong(yB_.x), eT2[4*k_+2], b2_);           \
        a3_ = fma2(__double_as_longlong(yA_.y), eT2[4*k_+3], a3_);           \
        b3_ = fma2(__double_as_longlong(yB_.y), eT2[4*k_+3], b3_);           \
    }                                                                        \
    unsigned long long aa_ = add2(add2(a0_,a1_), add2(a2_,a3_));             \
    unsigned long long bb_ = add2(add2(b0_,b1_), add2(b2_,b3_));             \
    float2 pa_ = unpack2(aa_), pb_ = unpack2(bb_);                           \
    float svA_ = pa_.x + pa_.y, svB_ = pb_.x + pb_.y;                        \
    svA_ += __shfl_xor_sync(0xffffffffu, svA_, 1);   /* combine halves */    \
    svB_ += __shfl_xor_sync(0xffffffffu, svB_, 1);                           \
    float nbA_ = svA_ * cjA_, nbB_ = svB_ * cjB_;                            \
    if (!h) { sh_beta[0][curA ^ 1][slotj] = nbA_;                            \
              sh_beta[1][curB ^ 1][slotj] = nbB_; }                          \
    __syncthreads();                      /* ONE barrier for both batches */ \
    curA ^= 1; curB ^= 1;                                                    \
} while (0)

// Single-batch tail step (renorm every step; tail is short).
#define CRF_STEP1(BI, CUR, SVAR, LO) do {                                    \
    const float* bp_ = sh_beta[BI][CUR];                                     \
    float lr_ = __logf(bp_[0]);                                              \
    SVAR += lr_;                                                             \
    float cj_ = __expf((LO) - lr_);                                          \
    const double2* ap_ = (const double2*)(bp_ + 68 * h);                     \
    unsigned long long a0_=0,a1_=0,a2_=0,a3_=0;                              \
    _Pragma("unroll")                                                        \
    for (int k_ = 0; k_ < 8; k_++) {                                         \
        double2 x_ = ap_[2*k_], y_ = ap_[2*k_+1];                            \
        a0_ = fma2(__double_as_longlong(x_.x), eT2[4*k_+0], a0_);            \
        a1_ = fma2(__double_as_longlong(x_.y), eT2[4*k_+1], a1_);            \
        a2_ = fma2(__double_as_longlong(y_.x), eT2[4*k_+2], a2_);            \
        a3_ = fma2(__double_as_longlong(y_.y), eT2[4*k_+3], a3_);            \
    }                                                                        \
    unsigned long long aa_ = add2(add2(a0_,a1_), add2(a2_,a3_));             \
    float2 pp_ = unpack2(aa_);                                               \
    float sv_ = pp_.x + pp_.y;                                               \
    sv_ += __shfl_xor_sync(0xffffffffu, sv_, 1);                             \
    float nb_ = sv_ * cj_;                                                   \
    if (!h) sh_beta[BI][CUR ^ 1][slotj] = nb_;                               \
    __syncthreads();                                                         \
    CUR ^= 1;                                                                \
} while (0)

// grid=128 CTAs, 256 threads, one CTA/SM. CTA c advances batches perm[2c]
// (A) and perm[2c+1] (B) IN THE SAME LOOP BODY: independent FMA chains share
// eT2 and hide each other's latency; one __syncthreads per fused step.
// Thread tau: column j=tau>>1, half h=tau&1 with 32 packed expT f32x2 regs
// (proven R6 layout). Linear-domain scan, renorm 1-in-4, 4x unrolled with
// static prefetch regs. Adjacent ranks => tiny single-batch tail.
__global__ __launch_bounds__(256, 1) void crf_forward_kernel(
    const float* __restrict__ logits,   // [B, T, K]
    const int*   __restrict__ labels,   // [B, T]
    const int*   __restrict__ seq_lens, // [B]
    const float* __restrict__ trans,    // [K, K] trans[i*K + j]
    float* __restrict__ out)
{
    __shared__ __align__(16) float sh_beta[2][2][136]; // [batch][buf][slot]
    __shared__ float sh_wredA[8], sh_wredB[8];
    __shared__ float sh_fin[8];
    __shared__ int   sh_last;

    const int c    = blockIdx.x;          // 0..127
    const int tau  = threadIdx.x;         // 0..255
    const int j    = tau >> 1;            // column 0..127
    const int h    = tau & 1;             // half
    const int lane = tau & 31;
    const int warp = tau >> 5;
    const int slotj = (j < 64) ? j : j + 4;

    const int bA = g_perm[2 * c];
    const int bB = g_perm[2 * c + 1];

    // expT rows [64h, 64h+64) of column j, packed over row-pairs
    unsigned long long eT2[32];
    #pragma unroll
    for (int k = 0; k < 32; k++) {
        float e0 = __expf(trans[(64 * h + 2 * k)     * Kn + j]);
        float e1 = __expf(trans[(64 * h + 2 * k + 1) * Kn + j]);
        eT2[k] = pack2(e0, e1);
    }

    const int LA = seq_lens[bA], LB = seq_lens[bB];   // 1..512
    const float* lgA  = logits + (size_t)bA * Tn * Kn;
    const float* lgB  = logits + (size_t)bB * Tn * Kn;
    const int*   lblA = labels + bA * Tn;
    const int*   lblB = labels + bB * Tn;

    // ---------- gold-path scores ----------
    float scA = 0.f, scB = 0.f;
    for (int t = tau; t < LA; t += 256) {
        int y = lblA[t];
        scA += lgA[t * Kn + y];
        if (t >= 1) scA += trans[lblA[t - 1] * Kn + y];
    }
    for (int t = tau; t < LB; t += 256) {
        int y = lblB[t];
        scB += lgB[t * Kn + y];
        if (t >= 1) scB += trans[lblB[t - 1] * Kn + y];
    }
    #pragma unroll
    for (int o = 16; o; o >>= 1) {
        scA += __shfl_xor_sync(0xffffffffu, scA, o);
        scB += __shfl_xor_sync(0xffffffffu, scB, o);
    }
    if (lane == 0) { sh_wredA[warp] = scA; sh_wredB[warp] = scB; }

    // beta_0 = exp(logits[:,0,:]) for both batches
    if (!h) {
        sh_beta[0][0][slotj] = __expf(lgA[j]);
        sh_beta[1][0][slotj] = __expf(lgB[j]);
    }

    // static prefetch regs: rows 1..4 of each batch (in-bounds, Tn=512)
    float pA0 = lgA[1*Kn+j], pA1 = lgA[2*Kn+j], pA2 = lgA[3*Kn+j], pA3 = lgA[4*Kn+j];
    float pB0 = lgB[1*Kn+j], pB1 = lgB[2*Kn+j], pB2 = lgB[3*Kn+j], pB3 = lgB[4*Kn+j];

    __syncthreads();
    float scoreA = 0.f, scoreB = 0.f;
    #pragma unroll
    for (int w = 0; w < 8; w++) { scoreA += sh_wredA[w]; scoreB += sh_wredB[w]; }

    // ---------- fused forward recursion over common prefix ----------
    float SA = 0.f, SB = 0.f;
    int   curA = 0, curB = 0;
    int   t = 1;
    const int Lmin = (LA < LB) ? LA : LB;
    #define ROWA(tt) lgA[(((tt) < Tn) ? (tt) : (Tn - 1)) * Kn + j]
    #define ROWB(tt) lgB[(((tt) < Tn) ? (tt) : (Tn - 1)) * Kn + j]
    while (t + 3 < Lmin) {
        CRF_STEP2(pA0, pB0, true);  pA0 = ROWA(t + 4); pB0 = ROWB(t + 4);
        CRF_STEP2(pA1, pB1, false); pA1 = ROWA(t + 5); pB1 = ROWB(t + 5);
        CRF_STEP2(pA2, pB2, false); pA2 = ROWA(t + 6); pB2 = ROWB(t + 6);
        CRF_STEP2(pA3, pB3, false); pA3 = ROWA(t + 7); pB3 = ROWB(t + 7);
        t += 4;
    }
    #undef ROWA
    #undef ROWB
    // fused remainder <= 3 steps; prefetch regs hold rows t..t+2
    if (t     < Lmin) CRF_STEP2(pA0, pB0, true);
    if (t + 1 < Lmin) CRF_STEP2(pA1, pB1, false);
    if (t + 2 < Lmin) CRF_STEP2(pA2, pB2, false);

    // ---------- single-batch tail on the longer batch (uniform branch) ----
    if (LA > LB) {
        for (int tt = Lmin; tt < LA; tt++) {
            float lo = lgA[tt * Kn + j];
            CRF_STEP1(0, curA, SA, lo);
        }
    } else if (LB > LA) {
        for (int tt = Lmin; tt < LB; tt++) {
            float lo = lgB[tt * Kn + j];
            CRF_STEP1(1, curB, SB, lo);
        }
    }

    // ---------- log_z for both batches ----------
    __syncthreads();                         // protect sh_wred reuse
    float vA = 0.f, vB = 0.f;
    if (tau < Kn) {
        int slot = (tau < 64) ? tau : tau + 4;
        vA = sh_beta[0][curA][slot];
        vB = sh_beta[1][curB][slot];
    }
    #pragma unroll
    for (int o = 16; o; o >>= 1) {
        vA += __shfl_xor_sync(0xffffffffu, vA, o);
        vB += __shfl_xor_sync(0xffffffffu, vB, o);
    }
    if (lane == 0) { sh_wredA[warp] = vA; sh_wredB[warp] = vB; }
    __syncthreads();

    if (tau == 0) {
        float sA = ((sh_wredA[0] + sh_wredA[1]) + (sh_wredA[2] + sh_wredA[3]))
                 + ((sh_wredA[4] + sh_wredA[5]) + (sh_wredA[6] + sh_wredA[7]));
        float sB = ((sh_wredB[0] + sh_wredB[1]) + (sh_wredB[2] + sh_wredB[3]))
                 + ((sh_wredB[4] + sh_wredB[5]) + (sh_wredB[6] + sh_wredB[7]));
        g_partial[bA] = SA + __logf(sA) - scoreA;    // per-batch NLL
        g_partial[bB] = SB + __logf(sB) - scoreB;
    }

    // ---------- fused final reduction: last CTA sums deterministically ----
    __syncthreads();
    if (tau == 0) {
        __threadfence();
        int d = atomicAdd(&g_done, 1);
        sh_last = (d == (Bn / 2 - 1));
    }
    __syncthreads();
    if (sh_last) {
        __threadfence();                 // see all CTAs' g_partial writes
        float w = g_partial[tau];        // fixed-tree: deterministic
        #pragma unroll
        for (int o = 16; o; o >>= 1) w += __shfl_xor_sync(0xffffffffu, w, o);
        if (lane == 0) sh_fin[warp] = w;
        __syncthreads();
        if (tau == 0) {
            float s = ((sh_fin[0] + sh_fin[1]) + (sh_fin[2] + sh_fin[3]))
                    + ((sh_fin[4] + sh_fin[5]) + (sh_fin[6] + sh_fin[7]));
            out[0]  = s;
            g_done  = 0;                 // reset for next graph replay
        }
    }
}

extern "C" void kernel_launch(void* const* d_in, const int* in_sizes, int n_in,
                              void* d_out, int out_size)
{
    const float* logits   = (const float*)d_in[0];
    const int*   labels   = (const int*)  d_in[1];
    const int*   seq_lens = (const int*)  d_in[2];
    const float* trans    = (const float*)d_in[3];
    float*       out      = (float*)d_out;

    crf_sched_kernel<<<32, 256>>>(seq_lens);
    crf_forward_kernel<<<Bn / 2, 256>>>(logits, labels, seq_lens, trans, out);
}